// round 4
// baseline (speedup 1.0000x reference)
#include <cuda_runtime.h>

#define Bq 64
#define Tq 256
#define Hq 1024
#define Oq 1024
#define BT (Bq * Tq)
#define LN_EPS 1e-5f

// ---------------- device scratch (no cudaMalloc allowed) ----------------
__device__ float g_bufA[BT * Hq];
__device__ float g_bufB[BT * Hq];
__device__ float g_h[Bq * Hq];
__device__ float g_stats[2][Bq][2];      // [parity][row][{sum,sumsq}]
__device__ unsigned int g_barcnt;        // zero-init
__device__ unsigned int g_bargen;

// ==================== SGEMM: C[M,N] = A[M,K] @ W[N,K]^T + bias ====================
// M=16384, N=K=1024. BM=BN=64, BK=16, 128 threads, 8x4 thread tile, double-buffered.
#define SG_BK 16
#define SG_PAD 68

__global__ __launch_bounds__(128) void sgemm_bias_kernel(
    const float* __restrict__ A, const float* __restrict__ W,
    const float* __restrict__ bias, float* __restrict__ C)
{
    __shared__ float As[2][SG_BK][SG_PAD];
    __shared__ float Bs[2][SG_BK][SG_PAD];
    const int tid = threadIdx.x;
    const int m0 = blockIdx.y * 64, n0 = blockIdx.x * 64;
    const int tm = tid >> 4, tn = tid & 15;       // 8 rows x 4 cols tile
    const int lr = tid >> 1, lh = (tid & 1) * 8;  // load row / k-half

    const float* Ap = A + (size_t)(m0 + lr) * Hq + lh;
    const float* Wp = W + (size_t)(n0 + lr) * Hq + lh;

    float acc[8][4];
#pragma unroll
    for (int i = 0; i < 8; i++)
#pragma unroll
        for (int j = 0; j < 4; j++) acc[i][j] = 0.0f;

    float4 pa0 = *(const float4*)Ap, pa1 = *(const float4*)(Ap + 4);
    float4 pb0 = *(const float4*)Wp, pb1 = *(const float4*)(Wp + 4);

#define STS_TILE(bi) do {                                                  \
    As[bi][lh+0][lr]=pa0.x; As[bi][lh+1][lr]=pa0.y;                        \
    As[bi][lh+2][lr]=pa0.z; As[bi][lh+3][lr]=pa0.w;                        \
    As[bi][lh+4][lr]=pa1.x; As[bi][lh+5][lr]=pa1.y;                        \
    As[bi][lh+6][lr]=pa1.z; As[bi][lh+7][lr]=pa1.w;                        \
    Bs[bi][lh+0][lr]=pb0.x; Bs[bi][lh+1][lr]=pb0.y;                        \
    Bs[bi][lh+2][lr]=pb0.z; Bs[bi][lh+3][lr]=pb0.w;                        \
    Bs[bi][lh+4][lr]=pb1.x; Bs[bi][lh+5][lr]=pb1.y;                        \
    Bs[bi][lh+6][lr]=pb1.z; Bs[bi][lh+7][lr]=pb1.w;                        \
} while (0)

    STS_TILE(0);
    __syncthreads();

    const int nkt = Hq / SG_BK;   // 64
    for (int kt = 0; kt < nkt; kt++) {
        const int buf = kt & 1;
        if (kt + 1 < nkt) {
            const float* ap = Ap + (kt + 1) * SG_BK;
            const float* wp = Wp + (kt + 1) * SG_BK;
            pa0 = *(const float4*)ap;  pa1 = *(const float4*)(ap + 4);
            pb0 = *(const float4*)wp;  pb1 = *(const float4*)(wp + 4);
        }
#pragma unroll
        for (int k = 0; k < SG_BK; k++) {
            float4 a0 = *(const float4*)&As[buf][k][tm * 8];
            float4 a1 = *(const float4*)&As[buf][k][tm * 8 + 4];
            float4 bv = *(const float4*)&Bs[buf][k][tn * 4];
            float av[8] = {a0.x,a0.y,a0.z,a0.w,a1.x,a1.y,a1.z,a1.w};
            float bw[4] = {bv.x,bv.y,bv.z,bv.w};
#pragma unroll
            for (int i = 0; i < 8; i++)
#pragma unroll
                for (int j = 0; j < 4; j++)
                    acc[i][j] = fmaf(av[i], bw[j], acc[i][j]);
        }
        if (kt + 1 < nkt) STS_TILE(buf ^ 1);
        __syncthreads();
    }

    float4 bv = *(const float4*)(bias + n0 + tn * 4);
#pragma unroll
    for (int i = 0; i < 8; i++) {
        float4 o;
        o.x = acc[i][0] + bv.x;  o.y = acc[i][1] + bv.y;
        o.z = acc[i][2] + bv.z;  o.w = acc[i][3] + bv.w;
        *(float4*)(C + (size_t)(m0 + tm * 8 + i) * Hq + n0 + tn * 4) = o;
    }
}

// ==================== persistent recurrent kernel ====================
// 128 CTAs (all co-resident on 148 SMs) x 128 threads. CTA b owns cols [8b,8b+8).
// Thread: cc = tid&7 -> column, rg = tid>>3 -> rows {rg, rg+16, rg+32, rg+48}.
#define RCTAS 128
#define RTHR 128
#define HS_PAD 260
#define RSMEM ((64 + 8) * HS_PAD * 4)

__device__ __forceinline__ void grid_barrier() {
    __syncthreads();
    if (threadIdx.x == 0) {
        volatile unsigned int* genp = &g_bargen;
        unsigned int gen = *genp;
        __threadfence();                       // publish (membar.gl -> CCTL.IVALL)
        if (atomicAdd(&g_barcnt, 1u) == RCTAS - 1u) {
            g_barcnt = 0u;
            __threadfence();
            atomicAdd(&g_bargen, 1u);
        } else {
            while (*genp == gen) __nanosleep(64);
        }
        __threadfence();                       // acquire: invalidate L1
    }
    __syncthreads();
}

__global__ __launch_bounds__(RTHR) void recur_kernel(
    const float* __restrict__ src,   // xw = x@Wx^T + bx, [B][T][H]
    float* __restrict__ dst,         // layer output, [B][T][H] (may alias src)
    const float* __restrict__ Wh,    // [H][H] row-major [out][in]
    const float* __restrict__ lng, const float* __restrict__ lnb)
{
    extern __shared__ float sm[];
    float* hs = sm;                        // [64][HS_PAD]
    float* ws = sm + 64 * HS_PAD;          // [8][HS_PAD]
    const int tid = threadIdx.x;
    const int cc = tid & 7;
    const int rg = tid >> 3;               // 0..15
    const int col = blockIdx.x * 8 + cc;
    const float gc = lng[col], bc = lnb[col];
    const float4* hg = (const float4*)g_h;                 // [64][256]
    const float4* wg = (const float4*)Wh;                  // [1024][256]

    for (int t = 0; t < Tq; t++) {
        const int p = t & 1;
        float z[4];
#pragma unroll
        for (int i = 0; i < 4; i++)
            z[i] = src[((size_t)(rg + 16 * i) * Tq + t) * Hq + col];

        if (t > 0) {
            float acc[4] = {0.f, 0.f, 0.f, 0.f};
            for (int c = 0; c < 4; c++) {          // k chunks of 256
                __syncthreads();
                // stage h[64][256] chunk (coalesced)
#pragma unroll
                for (int it = 0; it < 32; it++) {
                    int v = tid + it * RTHR;       // 0..4095
                    int row = v >> 6, kc = v & 63;
                    float4 f = hg[(size_t)row * 256 + c * 64 + kc];
                    *(float4*)&hs[row * HS_PAD + kc * 4] = f;
                }
                // stage w[8][256] chunk
#pragma unroll
                for (int it = 0; it < 4; it++) {
                    int v = tid + it * RTHR;       // 0..511
                    int row = v >> 6, kc = v & 63;
                    float4 f = wg[(size_t)(blockIdx.x * 8 + row) * 256 + c * 64 + kc];
                    *(float4*)&ws[row * HS_PAD + kc * 4] = f;
                }
                __syncthreads();
#pragma unroll 8
                for (int k4 = 0; k4 < 64; k4++) {
                    float4 wq = *(const float4*)&ws[cc * HS_PAD + k4 * 4];
#pragma unroll
                    for (int i = 0; i < 4; i++) {
                        float4 hq = *(const float4*)&hs[(rg + 16 * i) * HS_PAD + k4 * 4];
                        acc[i] = fmaf(hq.x, wq.x, acc[i]);
                        acc[i] = fmaf(hq.y, wq.y, acc[i]);
                        acc[i] = fmaf(hq.z, wq.z, acc[i]);
                        acc[i] = fmaf(hq.w, wq.w, acc[i]);
                    }
                }
            }
#pragma unroll
            for (int i = 0; i < 4; i++) z[i] += acc[i];
        }

        // per-row stats over this CTA's 8 columns (lanes cc=0..7 share rg)
        float s[4], q[4];
#pragma unroll
        for (int i = 0; i < 4; i++) { s[i] = z[i]; q[i] = z[i] * z[i]; }
#pragma unroll
        for (int d = 1; d < 8; d <<= 1)
#pragma unroll
            for (int i = 0; i < 4; i++) {
                s[i] += __shfl_xor_sync(0xffffffffu, s[i], d);
                q[i] += __shfl_xor_sync(0xffffffffu, q[i], d);
            }
        if (cc == 0) {
#pragma unroll
            for (int i = 0; i < 4; i++) {
                atomicAdd(&g_stats[p][rg + 16 * i][0], s[i]);
                atomicAdd(&g_stats[p][rg + 16 * i][1], q[i]);
            }
        }
        if (blockIdx.x == 0) ((float*)g_stats[p ^ 1])[tid] = 0.0f;  // clear other parity

        grid_barrier();   // stats complete & visible

        const float inv = 1.0f / 1024.0f;
#pragma unroll
        for (int i = 0; i < 4; i++) {
            const int r = rg + 16 * i;
            float mean = g_stats[p][r][0] * inv;
            float var  = g_stats[p][r][1] * inv - mean * mean;
            float hv = tanhf((z[i] - mean) * rsqrtf(var + LN_EPS) * gc + bc);
            dst[((size_t)r * Tq + t) * Hq + col] = hv;
            g_h[(size_t)r * Hq + col] = hv;
        }

        grid_barrier();   // h published before next step's stage reads
    }
}

__global__ void zero_stats_kernel() {
    ((float*)g_stats)[threadIdx.x] = 0.0f;   // 2*64*2 = 256
}

// ==================== launch ====================
extern "C" void kernel_launch(void* const* d_in, const int* in_sizes, int n_in,
                              void* d_out, int out_size)
{
    const float* x_in = (const float*)d_in[0];
    const float* Wx   = (const float*)d_in[1];
    const float* bx   = (const float*)d_in[2];
    const float* Wh   = (const float*)d_in[3];
    const float* lng  = (const float*)d_in[4];
    const float* lnb  = (const float*)d_in[5];
    const float* Wy   = (const float*)d_in[6];
    const float* by   = (const float*)d_in[7];

    float* bufA; cudaGetSymbolAddress((void**)&bufA, g_bufA);
    float* bufB; cudaGetSymbolAddress((void**)&bufB, g_bufB);

    // Output layout: prefer [x | y] concat; fall back if out_size says otherwise.
    float* out_x;
    float* out_y;
    int want_y = 1;
    if (out_size >= (long long)BT * (Hq + Oq)) {
        out_x = (float*)d_out; out_y = out_x + (size_t)BT * Hq;
    } else if (out_size == BT * Oq) {
        out_x = bufB; out_y = (float*)d_out;        // y only
    } else {
        out_x = (float*)d_out; out_y = bufA; want_y = 0;  // x only
    }

    cudaFuncSetAttribute(recur_kernel, cudaFuncAttributeMaxDynamicSharedMemorySize, RSMEM);

    const dim3 gg(Hq / 64, BT / 64);   // (16, 256)
    const size_t HH = (size_t)Hq * Hq;
    const float* cur = x_in;
    float* ping = bufA;
    float* pong = bufB;

    for (int l = 0; l < 4; l++) {
        float* dst = (l == 3) ? out_x : ping;
        sgemm_bias_kernel<<<gg, 128>>>(cur, Wx + l * HH, bx + (size_t)l * Hq, ping);
        zero_stats_kernel<<<1, 256>>>();
        recur_kernel<<<RCTAS, RTHR, RSMEM>>>(ping, dst, Wh + l * HH,
                                             lng + (size_t)l * Hq, lnb + (size_t)l * Hq);
        cur = dst;
        float* tmp = ping; ping = pong; pong = tmp;
    }
    if (want_y)
        sgemm_bias_kernel<<<gg, 128>>>(cur, Wy, by, out_y);
}

// round 5
// speedup vs baseline: 1.4418x; 1.4418x over previous
#include <cuda_runtime.h>

#define Bq 64
#define Tq 256
#define Hq 1024
#define Oq 1024
#define BT (Bq * Tq)
#define LN_EPS 1e-5f

typedef unsigned long long u64;

// ---------------- device scratch (no cudaMalloc allowed) ----------------
__device__ float g_bufA[BT * Hq];
__device__ float g_bufB[BT * Hq];
__device__ float g_h[Bq * Hq];
__device__ float g_stats[2][Bq][2];      // [parity][row][{sum,sumsq}]
__device__ unsigned int g_barcnt;        // zero-init
__device__ unsigned int g_bargen;

// packed fp32x2 FMA: acc += a * b (two fp32 lanes per instruction)
__device__ __forceinline__ void ffma2(u64& acc, u64 a, u64 b) {
    asm("fma.rn.f32x2 %0, %1, %2, %0;" : "+l"(acc) : "l"(a), "l"(b));
}
__device__ __forceinline__ u64 dup2(float v) {
    u64 r; unsigned u = __float_as_uint(v);
    asm("mov.b64 %0, {%1, %1};" : "=l"(r) : "r"(u));
    return r;
}

// ==================== SGEMM: C[M,N] = A[M,K] @ W[N,K]^T + bias ====================
// M=16384, N=K=1024. BM=BN=128, BK=8, 256 threads, 8x8/thread via f32x2, 2 CTAs/SM.
__global__ __launch_bounds__(256, 2) void sgemm_bias_kernel(
    const float* __restrict__ A, const float* __restrict__ W,
    const float* __restrict__ bias, float* __restrict__ C)
{
    __shared__ __align__(16) u64   As2[2][8][130];   // A values pre-duplicated (a,a)
    __shared__ __align__(16) float Bs[2][8][132];
    const int tid = threadIdx.x;
    const int m0 = blockIdx.y * 128, n0 = blockIdx.x * 128;
    const int ty = tid >> 4, tx = tid & 15;          // 16x16 thread grid, 8x8 tiles
    const int lr = tid >> 1, lk = (tid & 1) * 4;     // staging: row / k-quad

    const float* Ap = A + (size_t)(m0 + lr) * Hq + lk;
    const float* Wp = W + (size_t)(n0 + lr) * Hq + lk;

    u64 acc[8][4];
#pragma unroll
    for (int i = 0; i < 8; i++)
#pragma unroll
        for (int j = 0; j < 4; j++) acc[i][j] = 0ull;

    float4 pa = *(const float4*)Ap;
    float4 pw = *(const float4*)Wp;

#define SG_STS(bi) do {                                                    \
    As2[bi][lk + 0][lr] = dup2(pa.x); As2[bi][lk + 1][lr] = dup2(pa.y);    \
    As2[bi][lk + 2][lr] = dup2(pa.z); As2[bi][lk + 3][lr] = dup2(pa.w);    \
    Bs[bi][lk + 0][lr] = pw.x; Bs[bi][lk + 1][lr] = pw.y;                  \
    Bs[bi][lk + 2][lr] = pw.z; Bs[bi][lk + 3][lr] = pw.w;                  \
} while (0)

    SG_STS(0);
    __syncthreads();

    const int nkt = Hq / 8;   // 128
    for (int kt = 0; kt < nkt; kt++) {
        const int buf = kt & 1;
        if (kt + 1 < nkt) {
            pa = *(const float4*)(Ap + (kt + 1) * 8);
            pw = *(const float4*)(Wp + (kt + 1) * 8);
        }
#pragma unroll
        for (int k = 0; k < 8; k++) {
            ulonglong2 aa[4];
            aa[0] = *(const ulonglong2*)&As2[buf][k][ty * 8 + 0];
            aa[1] = *(const ulonglong2*)&As2[buf][k][ty * 8 + 2];
            aa[2] = *(const ulonglong2*)&As2[buf][k][ty * 8 + 4];
            aa[3] = *(const ulonglong2*)&As2[buf][k][ty * 8 + 6];
            ulonglong2 b01 = *(const ulonglong2*)&Bs[buf][k][tx * 8];
            ulonglong2 b23 = *(const ulonglong2*)&Bs[buf][k][tx * 8 + 4];
#pragma unroll
            for (int i = 0; i < 4; i++) {
                ffma2(acc[2*i+0][0], aa[i].x, b01.x);
                ffma2(acc[2*i+0][1], aa[i].x, b01.y);
                ffma2(acc[2*i+0][2], aa[i].x, b23.x);
                ffma2(acc[2*i+0][3], aa[i].x, b23.y);
                ffma2(acc[2*i+1][0], aa[i].y, b01.x);
                ffma2(acc[2*i+1][1], aa[i].y, b01.y);
                ffma2(acc[2*i+1][2], aa[i].y, b23.x);
                ffma2(acc[2*i+1][3], aa[i].y, b23.y);
            }
        }
        if (kt + 1 < nkt) SG_STS(buf ^ 1);
        __syncthreads();
    }

    float4 bv0 = *(const float4*)(bias + n0 + tx * 8);
    float4 bv1 = *(const float4*)(bias + n0 + tx * 8 + 4);
#pragma unroll
    for (int i = 0; i < 8; i++) {
        float2 c0 = *(float2*)&acc[i][0];
        float2 c1 = *(float2*)&acc[i][1];
        float2 c2 = *(float2*)&acc[i][2];
        float2 c3 = *(float2*)&acc[i][3];
        float4 o0 = {c0.x + bv0.x, c0.y + bv0.y, c1.x + bv0.z, c1.y + bv0.w};
        float4 o1 = {c2.x + bv1.x, c2.y + bv1.y, c3.x + bv1.z, c3.y + bv1.w};
        float* cp = C + (size_t)(m0 + ty * 8 + i) * Hq + n0 + tx * 8;
        *(float4*)cp = o0;
        *(float4*)(cp + 4) = o1;
    }
}

// ==================== persistent recurrent kernel ====================
// 128 CTAs x 256 threads. CTA b owns cols [8b,8b+8).
// Thread: cc = tid&7 -> column, rg = tid>>3 (0..31) -> rows {rg, rg+32}.
#define RCTAS 128
#define RTHR 256
#define HSP 260                      // floats per staged h row (pad: banks 4 apart)
#define WSP 1028                     // floats per persistent w row
#define HS_BUF (64 * HSP)
#define RSMEM ((2 * HS_BUF + 8 * WSP) * 4)   // 166,016 B

__device__ __forceinline__ void grid_barrier() {
    __syncthreads();
    if (threadIdx.x == 0) {
        volatile unsigned int* genp = &g_bargen;
        unsigned int gen = *genp;
        __threadfence();                        // publish prior writes (gpu scope)
        if (atomicAdd(&g_barcnt, 1u) == RCTAS - 1u) {
            g_barcnt = 0u;
            __threadfence();
            atomicAdd((unsigned int*)&g_bargen, 1u);
        } else {
            int spin = 0;
            while (*genp == gen) { if (++spin > 64) __nanosleep(32); }
        }
    }
    __syncthreads();
}

// stage h[:, c*256 .. c*256+256) -> hs_dst[64][HSP] via cp.async.cg (L2, coherent)
__device__ __forceinline__ void stage_chunk(float* hs_dst, int c, int tid) {
#pragma unroll
    for (int it = 0; it < 16; it++) {
        int v = tid + it * RTHR;                 // 0..4095 float4 units
        int row = v >> 6, kc = v & 63;
        const float* gp = g_h + (size_t)row * Hq + c * 256 + kc * 4;
        unsigned sp = (unsigned)__cvta_generic_to_shared(&hs_dst[row * HSP + kc * 4]);
        asm volatile("cp.async.cg.shared.global [%0], [%1], 16;" :: "r"(sp), "l"(gp) : "memory");
    }
    asm volatile("cp.async.commit_group;" ::: "memory");
}

__global__ __launch_bounds__(RTHR) void recur_kernel(
    const float* __restrict__ src,   // xw = x@Wx^T + bx, [B][T][H]
    float* __restrict__ dst,         // layer output, [B][T][H] (may alias src)
    const float* __restrict__ Wh,    // [H][H] row-major [out][in]
    const float* __restrict__ lng, const float* __restrict__ lnb)
{
    extern __shared__ float sm[];
    float* hs = sm;                  // [2][64][HSP]
    float* ws = sm + 2 * HS_BUF;     // [8][WSP] persistent Wh slice
    const int tid = threadIdx.x;
    const int cc = tid & 7;
    const int rg = tid >> 3;         // 0..31
    const int col = blockIdx.x * 8 + cc;

    // load this CTA's 8 Wh rows once (survives all steps; smem immune to L1 flush)
#pragma unroll
    for (int it = 0; it < 8; it++) {
        int v = tid + it * RTHR;     // 0..2047 float4 units
        int row = v >> 8, kc = v & 255;
        float4 f = *(const float4*)(Wh + (size_t)(blockIdx.x * 8 + row) * Hq + kc * 4);
        *(float4*)&ws[row * WSP + kc * 4] = f;
    }
    const float gc = lng[col], bc = lnb[col];
    __syncthreads();

    for (int t = 0; t < Tq; t++) {
        const int p = t & 1;
        float z0 = src[((size_t)rg * Tq + t) * Hq + col];
        float z1 = src[((size_t)(rg + 32) * Tq + t) * Hq + col];

        if (t > 0) {
            u64 acc0 = 0ull, acc1 = 0ull;        // packed (even,odd) partials
            stage_chunk(hs, 0, tid);
#pragma unroll
            for (int c = 0; c < 4; c++) {
                if (c < 3) {
                    stage_chunk(hs + ((c + 1) & 1) * HS_BUF, c + 1, tid);
                    asm volatile("cp.async.wait_group 1;" ::: "memory");
                } else {
                    asm volatile("cp.async.wait_group 0;" ::: "memory");
                }
                __syncthreads();
                const float* hb = hs + (c & 1) * HS_BUF;
                const float* wb = ws + cc * WSP + c * 256;
                const float* h0b = hb + rg * HSP;
                const float* h1b = hb + (rg + 32) * HSP;
#pragma unroll 8
                for (int k4 = 0; k4 < 64; k4++) {
                    ulonglong2 wq = *(const ulonglong2*)(wb + k4 * 4);
                    ulonglong2 h0 = *(const ulonglong2*)(h0b + k4 * 4);
                    ulonglong2 h1 = *(const ulonglong2*)(h1b + k4 * 4);
                    ffma2(acc0, h0.x, wq.x);
                    ffma2(acc0, h0.y, wq.y);
                    ffma2(acc1, h1.x, wq.x);
                    ffma2(acc1, h1.y, wq.y);
                }
                __syncthreads();
            }
            float2 a0 = *(float2*)&acc0; z0 += a0.x + a0.y;
            float2 a1 = *(float2*)&acc1; z1 += a1.x + a1.y;
        }

        // per-row stats over this CTA's 8 columns (lanes cc=0..7 share rg)
        float s0 = z0, q0 = z0 * z0, s1 = z1, q1 = z1 * z1;
#pragma unroll
        for (int d = 1; d < 8; d <<= 1) {
            s0 += __shfl_xor_sync(0xffffffffu, s0, d);
            q0 += __shfl_xor_sync(0xffffffffu, q0, d);
            s1 += __shfl_xor_sync(0xffffffffu, s1, d);
            q1 += __shfl_xor_sync(0xffffffffu, q1, d);
        }
        if (cc == 0) {
            atomicAdd(&g_stats[p][rg][0], s0);
            atomicAdd(&g_stats[p][rg][1], q0);
            atomicAdd(&g_stats[p][rg + 32][0], s1);
            atomicAdd(&g_stats[p][rg + 32][1], q1);
        }
        if (blockIdx.x == 0 && tid < 128)
            __stcg(&((float*)g_stats[p ^ 1])[tid], 0.0f);   // clear other parity

        grid_barrier();   // stats complete & visible

        const float inv = 1.0f / 1024.0f;
        {
            float mean = __ldcg(&g_stats[p][rg][0]) * inv;
            float var  = __ldcg(&g_stats[p][rg][1]) * inv - mean * mean;
            float hv = tanhf((z0 - mean) * rsqrtf(var + LN_EPS) * gc + bc);
            dst[((size_t)rg * Tq + t) * Hq + col] = hv;
            __stcg(&g_h[rg * Hq + col], hv);
        }
        {
            float mean = __ldcg(&g_stats[p][rg + 32][0]) * inv;
            float var  = __ldcg(&g_stats[p][rg + 32][1]) * inv - mean * mean;
            float hv = tanhf((z1 - mean) * rsqrtf(var + LN_EPS) * gc + bc);
            dst[((size_t)(rg + 32) * Tq + t) * Hq + col] = hv;
            __stcg(&g_h[(rg + 32) * Hq + col], hv);
        }

        grid_barrier();   // h published before next step's staging
    }
}

__global__ void zero_stats_kernel() {
    __stcg(&((float*)g_stats)[threadIdx.x], 0.0f);   // 2*64*2 = 256
}

// ==================== launch ====================
extern "C" void kernel_launch(void* const* d_in, const int* in_sizes, int n_in,
                              void* d_out, int out_size)
{
    const float* x_in = (const float*)d_in[0];
    const float* Wx   = (const float*)d_in[1];
    const float* bx   = (const float*)d_in[2];
    const float* Wh   = (const float*)d_in[3];
    const float* lng  = (const float*)d_in[4];
    const float* lnb  = (const float*)d_in[5];
    const float* Wy   = (const float*)d_in[6];
    const float* by   = (const float*)d_in[7];

    float* bufA; cudaGetSymbolAddress((void**)&bufA, g_bufA);
    float* bufB; cudaGetSymbolAddress((void**)&bufB, g_bufB);

    float* out_x;
    float* out_y;
    int want_y = 1;
    if (out_size >= (long long)BT * (Hq + Oq)) {
        out_x = (float*)d_out; out_y = out_x + (size_t)BT * Hq;
    } else if (out_size == BT * Oq) {
        out_x = bufB; out_y = (float*)d_out;
    } else {
        out_x = (float*)d_out; out_y = bufA; want_y = 0;
    }

    cudaFuncSetAttribute(recur_kernel, cudaFuncAttributeMaxDynamicSharedMemorySize, RSMEM);

    const dim3 gg(Hq / 128, BT / 128);   // (8, 128)
    const size_t HH = (size_t)Hq * Hq;
    const float* cur = x_in;
    float* ping = bufA;
    float* pong = bufB;

    for (int l = 0; l < 4; l++) {
        float* dst = (l == 3) ? out_x : ping;
        sgemm_bias_kernel<<<gg, 256>>>(cur, Wx + l * HH, bx + (size_t)l * Hq, ping);
        zero_stats_kernel<<<1, 256>>>();
        recur_kernel<<<RCTAS, RTHR, RSMEM>>>(ping, dst, Wh + l * HH,
                                             lng + (size_t)l * Hq, lnb + (size_t)l * Hq);
        cur = dst;
        float* tmp = ping; ping = pong; pong = tmp;
    }
    if (want_y)
        sgemm_bias_kernel<<<gg, 256>>>(cur, Wy, by, out_y);
}

// round 7
// speedup vs baseline: 1.6673x; 1.1564x over previous
#include <cuda_runtime.h>

#define Bq 64
#define Tq 256
#define Hq 1024
#define Oq 1024
#define BT (Bq * Tq)
#define LN_EPS 1e-5f

typedef unsigned long long u64;

// ---------------- device scratch (no cudaMalloc allowed) ----------------
__device__ float g_bufA[BT * Hq];
__device__ float g_bufB[BT * Hq];
__device__ float g_h[Bq * Hq];
__device__ float g_stats[2][Bq][2];      // [parity][row][{sum,sumsq}]
__device__ unsigned int g_barcnt;        // zero-init
__device__ unsigned int g_bargen;
__device__ unsigned int g_chunk[4];      // h-publish counters per 256-col chunk

// packed fp32x2 FMA
__device__ __forceinline__ void ffma2(u64& acc, u64 a, u64 b) {
    asm("fma.rn.f32x2 %0, %1, %2, %0;" : "+l"(acc) : "l"(a), "l"(b));
}
__device__ __forceinline__ u64 dup2(float v) {
    u64 r; unsigned u = __float_as_uint(v);
    asm("mov.b64 %0, {%1, %1};" : "=l"(r) : "r"(u));
    return r;
}
__device__ __forceinline__ unsigned ldg_u32(const unsigned* p) {
    unsigned v; asm volatile("ld.global.cg.u32 %0, [%1];" : "=r"(v) : "l"(p)); return v;
}

// ==================== SGEMM: C[M,N] = A[M,K] @ W[N,K]^T + bias ====================
// M=16384, N=K=1024. BM=BN=128, BK=16, 256 threads, 8x8/thread (4+4 split), f32x2.
__global__ __launch_bounds__(256, 2) void sgemm_bias_kernel(
    const float* __restrict__ A, const float* __restrict__ W,
    const float* __restrict__ bias, float* __restrict__ C)
{
    __shared__ __align__(16) float As[2][16][132];
    __shared__ __align__(16) float Bs[2][16][132];
    const int tid = threadIdx.x;
    const int m0 = blockIdx.y * 128, n0 = blockIdx.x * 128;
    const int ty = tid >> 4, tx = tid & 15;          // rows ty*4(+64), cols tx*4(+64)
    const int lr = tid >> 1, lk = (tid & 1) * 8;

    const float* Ap = A + (size_t)(m0 + lr) * Hq + lk;
    const float* Wp = W + (size_t)(n0 + lr) * Hq + lk;

    u64 acc[8][4];
#pragma unroll
    for (int i = 0; i < 8; i++)
#pragma unroll
        for (int j = 0; j < 4; j++) acc[i][j] = 0ull;

    float4 pa0 = *(const float4*)Ap, pa1 = *(const float4*)(Ap + 4);
    float4 pw0 = *(const float4*)Wp, pw1 = *(const float4*)(Wp + 4);

#define SG_STS(bi) do {                                                    \
    As[bi][lk+0][lr]=pa0.x; As[bi][lk+1][lr]=pa0.y;                        \
    As[bi][lk+2][lr]=pa0.z; As[bi][lk+3][lr]=pa0.w;                        \
    As[bi][lk+4][lr]=pa1.x; As[bi][lk+5][lr]=pa1.y;                        \
    As[bi][lk+6][lr]=pa1.z; As[bi][lk+7][lr]=pa1.w;                        \
    Bs[bi][lk+0][lr]=pw0.x; Bs[bi][lk+1][lr]=pw0.y;                        \
    Bs[bi][lk+2][lr]=pw0.z; Bs[bi][lk+3][lr]=pw0.w;                        \
    Bs[bi][lk+4][lr]=pw1.x; Bs[bi][lk+5][lr]=pw1.y;                        \
    Bs[bi][lk+6][lr]=pw1.z; Bs[bi][lk+7][lr]=pw1.w;                        \
} while (0)

    SG_STS(0);
    __syncthreads();

    const int nkt = Hq / 16;   // 64
    for (int kt = 0; kt < nkt; kt++) {
        const int buf = kt & 1;
        if (kt + 1 < nkt) {
            const float* ap = Ap + (kt + 1) * 16;
            const float* wp = Wp + (kt + 1) * 16;
            pa0 = *(const float4*)ap;  pa1 = *(const float4*)(ap + 4);
            pw0 = *(const float4*)wp;  pw1 = *(const float4*)(wp + 4);
        }
#pragma unroll
        for (int k = 0; k < 16; k++) {
            float4 af0 = *(const float4*)&As[buf][k][ty * 4];
            float4 af1 = *(const float4*)&As[buf][k][64 + ty * 4];
            ulonglong2 bq0 = *(const ulonglong2*)&Bs[buf][k][tx * 4];
            ulonglong2 bq1 = *(const ulonglong2*)&Bs[buf][k][64 + tx * 4];
            u64 ad[8];
            ad[0] = dup2(af0.x); ad[1] = dup2(af0.y);
            ad[2] = dup2(af0.z); ad[3] = dup2(af0.w);
            ad[4] = dup2(af1.x); ad[5] = dup2(af1.y);
            ad[6] = dup2(af1.z); ad[7] = dup2(af1.w);
#pragma unroll
            for (int i = 0; i < 8; i++) {
                ffma2(acc[i][0], ad[i], bq0.x);
                ffma2(acc[i][1], ad[i], bq0.y);
                ffma2(acc[i][2], ad[i], bq1.x);
                ffma2(acc[i][3], ad[i], bq1.y);
            }
        }
        if (kt + 1 < nkt) SG_STS(buf ^ 1);
        __syncthreads();
    }

    float4 bv0 = *(const float4*)(bias + n0 + tx * 4);
    float4 bv1 = *(const float4*)(bias + n0 + 64 + tx * 4);
#pragma unroll
    for (int i = 0; i < 8; i++) {
        const int r = (i < 4) ? (ty * 4 + i) : (64 + ty * 4 + (i - 4));
        float2 c0 = *(float2*)&acc[i][0];
        float2 c1 = *(float2*)&acc[i][1];
        float2 c2 = *(float2*)&acc[i][2];
        float2 c3 = *(float2*)&acc[i][3];
        float4 o0 = {c0.x + bv0.x, c0.y + bv0.y, c1.x + bv0.z, c1.y + bv0.w};
        float4 o1 = {c2.x + bv1.x, c2.y + bv1.y, c3.x + bv1.z, c3.y + bv1.w};
        float* cp = C + (size_t)(m0 + r) * Hq + n0;
        *(float4*)(cp + tx * 4) = o0;
        *(float4*)(cp + 64 + tx * 4) = o1;
    }
}

// ==================== persistent recurrent kernel ====================
#define RCTAS 128
#define RTHR 256
#define HSP 260
#define WSP 1028
#define HS_BUF (64 * HSP)
#define RSMEM ((2 * HS_BUF + 8 * WSP) * 4)

__device__ __forceinline__ void grid_barrier() {
    __threadfence();                            // release: all threads' prior L2 ops
    __syncthreads();
    if (threadIdx.x == 0) {
        unsigned gen = ldg_u32(&g_bargen);
        if (atomicAdd(&g_barcnt, 1u) == RCTAS - 1u) {
            g_barcnt = 0u;
            __threadfence();
            atomicAdd(&g_bargen, 1u);
        } else {
            int s = 0;
            while (ldg_u32(&g_bargen) == gen) { if (++s > 8) __nanosleep(40); }
        }
    }
    __syncthreads();
}

// stage h[:, c*256 .. +256) -> dst[64][HSP] via cp.async.cg
__device__ __forceinline__ void stage_chunk(float* dst, int c, int tid) {
#pragma unroll
    for (int it = 0; it < 16; it++) {
        int v = tid + it * RTHR;
        int row = v >> 6, kc = v & 63;
        const float* gp = g_h + (size_t)row * Hq + c * 256 + kc * 4;
        unsigned sp = (unsigned)__cvta_generic_to_shared(&dst[row * HSP + kc * 4]);
        asm volatile("cp.async.cg.shared.global [%0], [%1], 16;" :: "r"(sp), "l"(gp) : "memory");
    }
    asm volatile("cp.async.commit_group;" ::: "memory");
}

__global__ __launch_bounds__(RTHR) void recur_kernel(
    const float* __restrict__ src, float* __restrict__ dst,
    const float* __restrict__ Wh,
    const float* __restrict__ lng, const float* __restrict__ lnb)
{
    extern __shared__ float sm[];
    float* hs = sm;                  // [2][64][HSP]
    float* ws = sm + 2 * HS_BUF;     // [8][WSP] persistent Wh slice
    const int tid = threadIdx.x;
    const int cc = tid & 7;
    const int rg = tid >> 3;         // 0..31 -> rows {rg, rg+32}
    const int col = blockIdx.x * 8 + cc;

#pragma unroll
    for (int it = 0; it < 8; it++) {
        int v = tid + it * RTHR;
        int row = v >> 8, kc = v & 255;
        float4 f = *(const float4*)(Wh + (size_t)(blockIdx.x * 8 + row) * Hq + kc * 4);
        *(float4*)&ws[row * WSP + kc * 4] = f;
    }
    const float gc = lng[col], bc = lnb[col];
    __syncthreads();

    for (int t = 0; t < Tq; t++) {
        const int p = t & 1;
        float z0 = src[((size_t)rg * Tq + t) * Hq + col];
        float z1 = src[((size_t)(rg + 32) * Tq + t) * Hq + col];

        if (t > 0) {
            u64 acc0 = 0ull, acc1 = 0ull;
            const unsigned tgt = 32u * (unsigned)t;
#pragma unroll
            for (int c = 0; c < 4; c++) {
                if (tid == 0) { while (ldg_u32(&g_chunk[c]) < tgt) { } }
                __syncthreads();                       // flag seen; prev buf free
                stage_chunk(hs + (c & 1) * HS_BUF, c, tid);
                if (c >= 1) {
                    asm volatile("cp.async.wait_group 1;" ::: "memory");
                    __syncthreads();
                    const float* hb = hs + ((c - 1) & 1) * HS_BUF;
                    const float* wb = ws + cc * WSP + (c - 1) * 256;
                    const float* h0b = hb + rg * HSP;
                    const float* h1b = hb + (rg + 32) * HSP;
#pragma unroll 8
                    for (int k4 = 0; k4 < 64; k4++) {
                        ulonglong2 wq = *(const ulonglong2*)(wb + k4 * 4);
                        ulonglong2 h0 = *(const ulonglong2*)(h0b + k4 * 4);
                        ulonglong2 h1 = *(const ulonglong2*)(h1b + k4 * 4);
                        ffma2(acc0, h0.x, wq.x);
                        ffma2(acc0, h0.y, wq.y);
                        ffma2(acc1, h1.x, wq.x);
                        ffma2(acc1, h1.y, wq.y);
                    }
                }
            }
            asm volatile("cp.async.wait_group 0;" ::: "memory");
            __syncthreads();
            {
                const float* hb = hs + 1 * HS_BUF;     // chunk 3 -> buf 1
                const float* wb = ws + cc * WSP + 3 * 256;
                const float* h0b = hb + rg * HSP;
                const float* h1b = hb + (rg + 32) * HSP;
#pragma unroll 8
                for (int k4 = 0; k4 < 64; k4++) {
                    ulonglong2 wq = *(const ulonglong2*)(wb + k4 * 4);
                    ulonglong2 h0 = *(const ulonglong2*)(h0b + k4 * 4);
                    ulonglong2 h1 = *(const ulonglong2*)(h1b + k4 * 4);
                    ffma2(acc0, h0.x, wq.x);
                    ffma2(acc0, h0.y, wq.y);
                    ffma2(acc1, h1.x, wq.x);
                    ffma2(acc1, h1.y, wq.y);
                }
            }
            float2 a0 = *(float2*)&acc0; z0 += a0.x + a0.y;
            float2 a1 = *(float2*)&acc1; z1 += a1.x + a1.y;
        }

        float s0 = z0, q0 = z0 * z0, s1 = z1, q1 = z1 * z1;
#pragma unroll
        for (int d = 1; d < 8; d <<= 1) {
            s0 += __shfl_xor_sync(0xffffffffu, s0, d);
            q0 += __shfl_xor_sync(0xffffffffu, q0, d);
            s1 += __shfl_xor_sync(0xffffffffu, s1, d);
            q1 += __shfl_xor_sync(0xffffffffu, q1, d);
        }
        if (cc == 0) {
            atomicAdd(&g_stats[p][rg][0], s0);
            atomicAdd(&g_stats[p][rg][1], q0);
            atomicAdd(&g_stats[p][rg + 32][0], s1);
            atomicAdd(&g_stats[p][rg + 32][1], q1);
        }
        if (blockIdx.x == 0 && tid < 128)
            __stcg(&((float*)g_stats[p ^ 1])[tid], 0.0f);

        grid_barrier();   // stats complete & visible

        const float inv = 1.0f / 1024.0f;
        float m0v = __ldcg(&g_stats[p][rg][0]) * inv;
        float v0v = __ldcg(&g_stats[p][rg][1]) * inv - m0v * m0v;
        float hv0 = tanhf((z0 - m0v) * rsqrtf(v0v + LN_EPS) * gc + bc);
        float m1v = __ldcg(&g_stats[p][rg + 32][0]) * inv;
        float v1v = __ldcg(&g_stats[p][rg + 32][1]) * inv - m1v * m1v;
        float hv1 = tanhf((z1 - m1v) * rsqrtf(v1v + LN_EPS) * gc + bc);

        __stcg(&g_h[rg * Hq + col], hv0);
        __stcg(&g_h[(rg + 32) * Hq + col], hv1);
        __threadfence();                               // publish h before flag
        __syncthreads();
        if (tid == 0) atomicAdd(&g_chunk[blockIdx.x >> 5], 1u);

        dst[((size_t)rg * Tq + t) * Hq + col] = hv0;   // off critical path
        dst[((size_t)(rg + 32) * Tq + t) * Hq + col] = hv1;
    }
}

__global__ void zero_misc_kernel() {
    int i = threadIdx.x;
    __stcg(&((float*)g_stats)[i], 0.0f);   // 256
    if (i < 4) g_chunk[i] = 0u;
}

// ==================== launch ====================
extern "C" void kernel_launch(void* const* d_in, const int* in_sizes, int n_in,
                              void* d_out, int out_size)
{
    const float* x_in = (const float*)d_in[0];
    const float* Wx   = (const float*)d_in[1];
    const float* bx   = (const float*)d_in[2];
    const float* Wh   = (const float*)d_in[3];
    const float* lng  = (const float*)d_in[4];
    const float* lnb  = (const float*)d_in[5];
    const float* Wy   = (const float*)d_in[6];
    const float* by   = (const float*)d_in[7];

    float* bufA; cudaGetSymbolAddress((void**)&bufA, g_bufA);
    float* bufB; cudaGetSymbolAddress((void**)&bufB, g_bufB);

    float* out_x;
    float* out_y;
    int want_y = 1;
    if (out_size >= (long long)BT * (Hq + Oq)) {
        out_x = (float*)d_out; out_y = out_x + (size_t)BT * Hq;
    } else if (out_size == BT * Oq) {
        out_x = bufB; out_y = (float*)d_out;
    } else {
        out_x = (float*)d_out; out_y = bufA; want_y = 0;
    }

    cudaFuncSetAttribute(recur_kernel, cudaFuncAttributeMaxDynamicSharedMemorySize, RSMEM);

    const dim3 gg(Hq / 128, BT / 128);   // (8, 128)
    const size_t HH = (size_t)Hq * Hq;
    const float* cur = x_in;
    float* ping = bufA;
    float* pong = bufB;

    for (int l = 0; l < 4; l++) {
        float* dst = (l == 3) ? out_x : ping;
        sgemm_bias_kernel<<<gg, 256>>>(cur, Wx + l * HH, bx + (size_t)l * Hq, ping);
        zero_misc_kernel<<<1, 256>>>();
        recur_kernel<<<RCTAS, RTHR, RSMEM>>>(ping, dst, Wh + l * HH,
                                             lng + (size_t)l * Hq, lnb + (size_t)l * Hq);
        cur = dst;
        float* tmp = ping; ping = pong; pong = tmp;
    }
    if (want_y)
        sgemm_bias_kernel<<<gg, 256>>>(cur, Wy, by, out_y);
}

// round 12
// speedup vs baseline: 1.6947x; 1.0164x over previous
#include <cuda_runtime.h>

#define Bq 64
#define Tq 256
#define Hq 1024
#define Oq 1024
#define BT (Bq * Tq)
#define LN_EPS 1e-5f

typedef unsigned long long u64;

// ---------------- device scratch (no cudaMalloc allowed) ----------------
__device__ float g_bufA[BT * Hq];
__device__ float g_bufB[BT * Hq];
__device__ float g_h[Bq * Hq];
__device__ float g_stats[2][Bq][2];      // [parity][row][{sum,sumsq}]
__device__ unsigned int g_chunk[4];      // h-publish counters per 256-col chunk
__device__ unsigned int g_scnt[2];       // stats-ready counters per parity

// packed fp32x2 FMA
__device__ __forceinline__ void ffma2(u64& acc, u64 a, u64 b) {
    asm("fma.rn.f32x2 %0, %1, %2, %0;" : "+l"(acc) : "l"(a), "l"(b));
}
__device__ __forceinline__ u64 dup2(float v) {
    u64 r; unsigned u = __float_as_uint(v);
    asm("mov.b64 %0, {%1, %1};" : "=l"(r) : "r"(u));
    return r;
}
__device__ __forceinline__ unsigned ld_acq(const unsigned* p) {
    unsigned v; asm volatile("ld.acquire.gpu.global.u32 %0, [%1];" : "=r"(v) : "l"(p)); return v;
}
__device__ __forceinline__ void red_rel_add(unsigned* p, unsigned v) {
    asm volatile("red.release.gpu.global.add.u32 [%0], %1;" :: "l"(p), "r"(v) : "memory");
}
__device__ __forceinline__ void stg_u32(unsigned* p, unsigned v) {
    asm volatile("st.global.cg.u32 [%0], %1;" :: "l"(p), "r"(v) : "memory");
}

// ==================== SGEMM: C[M,N] = A[M,K] @ W[N,K]^T + bias ====================
// BM=BN=128, BK=16, 256 threads, 8x8/thread (4+4 split), A pre-duplicated f32x2.
__global__ __launch_bounds__(256, 2) void sgemm_bias_kernel(
    const float* __restrict__ A, const float* __restrict__ W,
    const float* __restrict__ bias, float* __restrict__ C)
{
    __shared__ __align__(16) u64   As2[2][16][130];
    __shared__ __align__(16) float Bs[2][16][132];
    const int tid = threadIdx.x;
    const int m0 = blockIdx.y * 128, n0 = blockIdx.x * 128;
    const int ty = tid >> 4, tx = tid & 15;
    const int lr = tid >> 1, lk = (tid & 1) * 8;

    const float* Ap = A + (size_t)(m0 + lr) * Hq + lk;
    const float* Wp = W + (size_t)(n0 + lr) * Hq + lk;

    u64 acc[8][4];
#pragma unroll
    for (int i = 0; i < 8; i++)
#pragma unroll
        for (int j = 0; j < 4; j++) acc[i][j] = 0ull;

    float4 pa0 = *(const float4*)Ap, pa1 = *(const float4*)(Ap + 4);
    float4 pw0 = *(const float4*)Wp, pw1 = *(const float4*)(Wp + 4);

#define SG_STS(bi) do {                                                    \
    As2[bi][lk+0][lr]=dup2(pa0.x); As2[bi][lk+1][lr]=dup2(pa0.y);          \
    As2[bi][lk+2][lr]=dup2(pa0.z); As2[bi][lk+3][lr]=dup2(pa0.w);          \
    As2[bi][lk+4][lr]=dup2(pa1.x); As2[bi][lk+5][lr]=dup2(pa1.y);          \
    As2[bi][lk+6][lr]=dup2(pa1.z); As2[bi][lk+7][lr]=dup2(pa1.w);          \
    Bs[bi][lk+0][lr]=pw0.x; Bs[bi][lk+1][lr]=pw0.y;                        \
    Bs[bi][lk+2][lr]=pw0.z; Bs[bi][lk+3][lr]=pw0.w;                        \
    Bs[bi][lk+4][lr]=pw1.x; Bs[bi][lk+5][lr]=pw1.y;                        \
    Bs[bi][lk+6][lr]=pw1.z; Bs[bi][lk+7][lr]=pw1.w;                        \
} while (0)

    SG_STS(0);
    __syncthreads();

    const int nkt = Hq / 16;   // 64
    for (int kt = 0; kt < nkt; kt++) {
        const int buf = kt & 1;
        if (kt + 1 < nkt) {
            const float* ap = Ap + (kt + 1) * 16;
            const float* wp = Wp + (kt + 1) * 16;
            pa0 = *(const float4*)ap;  pa1 = *(const float4*)(ap + 4);
            pw0 = *(const float4*)wp;  pw1 = *(const float4*)(wp + 4);
        }
#pragma unroll
        for (int k = 0; k < 16; k++) {
            ulonglong2 a01 = *(const ulonglong2*)&As2[buf][k][ty * 4];
            ulonglong2 a23 = *(const ulonglong2*)&As2[buf][k][ty * 4 + 2];
            ulonglong2 a45 = *(const ulonglong2*)&As2[buf][k][64 + ty * 4];
            ulonglong2 a67 = *(const ulonglong2*)&As2[buf][k][64 + ty * 4 + 2];
            ulonglong2 bq0 = *(const ulonglong2*)&Bs[buf][k][tx * 4];
            ulonglong2 bq1 = *(const ulonglong2*)&Bs[buf][k][64 + tx * 4];
            u64 ad[8] = {a01.x, a01.y, a23.x, a23.y, a45.x, a45.y, a67.x, a67.y};
#pragma unroll
            for (int i = 0; i < 8; i++) {
                ffma2(acc[i][0], ad[i], bq0.x);
                ffma2(acc[i][1], ad[i], bq0.y);
                ffma2(acc[i][2], ad[i], bq1.x);
                ffma2(acc[i][3], ad[i], bq1.y);
            }
        }
        if (kt + 1 < nkt) SG_STS(buf ^ 1);
        __syncthreads();
    }

    float4 bv0 = *(const float4*)(bias + n0 + tx * 4);
    float4 bv1 = *(const float4*)(bias + n0 + 64 + tx * 4);
#pragma unroll
    for (int i = 0; i < 8; i++) {
        const int r = (i < 4) ? (ty * 4 + i) : (64 + ty * 4 + (i - 4));
        float2 c0 = *(float2*)&acc[i][0];
        float2 c1 = *(float2*)&acc[i][1];
        float2 c2 = *(float2*)&acc[i][2];
        float2 c3 = *(float2*)&acc[i][3];
        float4 o0 = {c0.x + bv0.x, c0.y + bv0.y, c1.x + bv0.z, c1.y + bv0.w};
        float4 o1 = {c2.x + bv1.x, c2.y + bv1.y, c3.x + bv1.z, c3.y + bv1.w};
        float* cp = C + (size_t)(m0 + r) * Hq + n0;
        *(float4*)(cp + tx * 4) = o0;
        *(float4*)(cp + 64 + tx * 4) = o1;
    }
}

// ==================== persistent recurrent kernel ====================
#define RCTAS 128
#define RTHR 256
#define HSP 260
#define WSP 1028
#define HS_BUF (64 * HSP)
#define RSMEM ((2 * HS_BUF + 8 * WSP) * 4)

// stage h[:, c*256 .. +256) -> dst[64][HSP] via cp.async.cg
__device__ __forceinline__ void stage_chunk(float* dst, int c, int tid) {
#pragma unroll
    for (int it = 0; it < 16; it++) {
        int v = tid + it * RTHR;
        int row = v >> 6, kc = v & 63;
        const float* gp = g_h + (size_t)row * Hq + c * 256 + kc * 4;
        unsigned sp = (unsigned)__cvta_generic_to_shared(&dst[row * HSP + kc * 4]);
        asm volatile("cp.async.cg.shared.global [%0], [%1], 16;" :: "r"(sp), "l"(gp) : "memory");
    }
    asm volatile("cp.async.commit_group;" ::: "memory");
}

__device__ __forceinline__ void compute_chunk(
    const float* hb, const float* wb, int rg, u64& acc0, u64& acc1)
{
    const float* h0b = hb + rg * HSP;
    const float* h1b = hb + (rg + 32) * HSP;
#pragma unroll 8
    for (int k4 = 0; k4 < 64; k4++) {
        ulonglong2 wq = *(const ulonglong2*)(wb + k4 * 4);
        ulonglong2 h0 = *(const ulonglong2*)(h0b + k4 * 4);
        ulonglong2 h1 = *(const ulonglong2*)(h1b + k4 * 4);
        ffma2(acc0, h0.x, wq.x);
        ffma2(acc0, h0.y, wq.y);
        ffma2(acc1, h1.x, wq.x);
        ffma2(acc1, h1.y, wq.y);
    }
}

#define CPWAIT(n) asm volatile("cp.async.wait_group " #n ";" ::: "memory")

__global__ __launch_bounds__(RTHR) void recur_kernel(
    const float* __restrict__ src, float* __restrict__ dst,
    const float* __restrict__ Wh,
    const float* __restrict__ lng, const float* __restrict__ lnb)
{
    extern __shared__ float sm[];
    float* hs = sm;                  // [2][64][HSP]
    float* ws = sm + 2 * HS_BUF;     // [8][WSP] persistent Wh slice
    const int tid = threadIdx.x;
    const int cc = tid & 7;
    const int rg = tid >> 3;         // rows {rg, rg+32}
    const int col = blockIdx.x * 8 + cc;

#pragma unroll
    for (int it = 0; it < 8; it++) {
        int v = tid + it * RTHR;
        int row = v >> 8, kc = v & 255;
        float4 f = *(const float4*)(Wh + (size_t)(blockIdx.x * 8 + row) * Hq + kc * 4);
        *(float4*)&ws[row * WSP + kc * 4] = f;
    }
    const float gc = lng[col], bc = lnb[col];
    __syncthreads();

    for (int t = 0; t < Tq; t++) {
        const int p = t & 1;
        float z0 = src[((size_t)rg * Tq + t) * Hq + col];
        float z1 = src[((size_t)(rg + 32) * Tq + t) * Hq + col];

        if (t > 0) {
            u64 acc0 = 0ull, acc1 = 0ull;
            const unsigned tgt = 32u * (unsigned)t;

            // single poll point: threads 0..3 each watch one chunk flag (sparse!)
            if (tid < 4) {
                if (ld_acq(&g_chunk[tid]) < tgt) {
                    do { __nanosleep(30); } while (ld_acq(&g_chunk[tid]) < tgt);
                }
            }
            __syncthreads();       // all h chunks of step t-1 published & visible

            stage_chunk(hs, 0, tid);
            stage_chunk(hs + HS_BUF, 1, tid);

            // safe point: all flags >= 32t => every CTA done reading parity p^1
            if (blockIdx.x == 0) {
                if (tid < 128) __stcg(&((float*)g_stats[p ^ 1])[tid], 0.0f);
                if (tid == 128) stg_u32(&g_scnt[p ^ 1], 0u);
            }

            CPWAIT(1);  __syncthreads();
            compute_chunk(hs, ws + cc * WSP, rg, acc0, acc1);
            __syncthreads();
            stage_chunk(hs, 2, tid);

            CPWAIT(1);  __syncthreads();
            compute_chunk(hs + HS_BUF, ws + cc * WSP + 256, rg, acc0, acc1);
            __syncthreads();
            stage_chunk(hs + HS_BUF, 3, tid);

            CPWAIT(1);  __syncthreads();
            compute_chunk(hs, ws + cc * WSP + 512, rg, acc0, acc1);

            CPWAIT(0);  __syncthreads();
            compute_chunk(hs + HS_BUF, ws + cc * WSP + 768, rg, acc0, acc1);

            float2 a0 = *(float2*)&acc0; z0 += a0.x + a0.y;
            float2 a1 = *(float2*)&acc1; z1 += a1.x + a1.y;
        }

        // per-row stats over this CTA's 8 columns
        float s0 = z0, q0 = z0 * z0, s1 = z1, q1 = z1 * z1;
#pragma unroll
        for (int d = 1; d < 8; d <<= 1) {
            s0 += __shfl_xor_sync(0xffffffffu, s0, d);
            q0 += __shfl_xor_sync(0xffffffffu, q0, d);
            s1 += __shfl_xor_sync(0xffffffffu, s1, d);
            q1 += __shfl_xor_sync(0xffffffffu, q1, d);
        }
        if (cc == 0) {
            atomicAdd(&g_stats[p][rg][0], s0);
            atomicAdd(&g_stats[p][rg][1], q0);
            atomicAdd(&g_stats[p][rg + 32][0], s1);
            atomicAdd(&g_stats[p][rg + 32][1], q1);
        }
        __syncthreads();
        if (tid == 0) {
            red_rel_add(&g_scnt[p], 1u);      // release: REDs above are prior
            if (ld_acq(&g_scnt[p]) < (unsigned)RCTAS) {
                do { __nanosleep(30); } while (ld_acq(&g_scnt[p]) < (unsigned)RCTAS);
            }
        }
        __syncthreads();                      // stats of all CTAs visible

        const float inv = 1.0f / 1024.0f;
        float m0v = __ldcg(&g_stats[p][rg][0]) * inv;
        float v0v = __ldcg(&g_stats[p][rg][1]) * inv - m0v * m0v;
        float hv0 = tanhf((z0 - m0v) * rsqrtf(v0v + LN_EPS) * gc + bc);
        float m1v = __ldcg(&g_stats[p][rg + 32][0]) * inv;
        float v1v = __ldcg(&g_stats[p][rg + 32][1]) * inv - m1v * m1v;
        float hv1 = tanhf((z1 - m1v) * rsqrtf(v1v + LN_EPS) * gc + bc);

        __stcg(&g_h[rg * Hq + col], hv0);
        __stcg(&g_h[(rg + 32) * Hq + col], hv1);
        __syncthreads();                      // all h stores issued
        if (tid == 0) red_rel_add(&g_chunk[blockIdx.x >> 5], 1u);  // publish h

        dst[((size_t)rg * Tq + t) * Hq + col] = hv0;    // off critical path
        dst[((size_t)(rg + 32) * Tq + t) * Hq + col] = hv1;
    }
}

__global__ void zero_misc_kernel() {
    int i = threadIdx.x;
    __stcg(&((float*)g_stats)[i], 0.0f);   // 256 = both parities
    if (i < 4) stg_u32(&g_chunk[i], 0u);
    if (i < 2) stg_u32(&g_scnt[i], 0u);
}

// ==================== launch ====================
extern "C" void kernel_launch(void* const* d_in, const int* in_sizes, int n_in,
                              void* d_out, int out_size)
{
    const float* x_in = (const float*)d_in[0];
    const float* Wx   = (const float*)d_in[1];
    const float* bx   = (const float*)d_in[2];
    const float* Wh   = (const float*)d_in[3];
    const float* lng  = (const float*)d_in[4];
    const float* lnb  = (const float*)d_in[5];
    const float* Wy   = (const float*)d_in[6];
    const float* by   = (const float*)d_in[7];

    float* bufA; cudaGetSymbolAddress((void**)&bufA, g_bufA);
    float* bufB; cudaGetSymbolAddress((void**)&bufB, g_bufB);

    float* out_x;
    float* out_y;
    int want_y = 1;
    if (out_size >= (long long)BT * (Hq + Oq)) {
        out_x = (float*)d_out; out_y = out_x + (size_t)BT * Hq;
    } else if (out_size == BT * Oq) {
        out_x = bufB; out_y = (float*)d_out;
    } else {
        out_x = (float*)d_out; out_y = bufA; want_y = 0;
    }

    cudaFuncSetAttribute(recur_kernel, cudaFuncAttributeMaxDynamicSharedMemorySize, RSMEM);

    const dim3 gg(Hq / 128, BT / 128);   // (8, 128)
    const size_t HH = (size_t)Hq * Hq;
    const float* cur = x_in;
    float* ping = bufA;
    float* pong = bufB;

    for (int l = 0; l < 4; l++) {
        float* dst = (l == 3) ? out_x : ping;
        sgemm_bias_kernel<<<gg, 256>>>(cur, Wx + l * HH, bx + (size_t)l * Hq, ping);
        zero_misc_kernel<<<1, 256>>>();
        recur_kernel<<<RCTAS, RTHR, RSMEM>>>(ping, dst, Wh + l * HH,
                                             lng + (size_t)l * Hq, lnb + (size_t)l * Hq);
        cur = dst;
        float* tmp = ping; ping = pong; pong = tmp;
    }
    if (want_y)
        sgemm_bias_kernel<<<gg, 256>>>(cur, Wy, by, out_y);
}